// round 1
// baseline (speedup 1.0000x reference)
#include <cuda_runtime.h>
#include <cstdint>

// Problem constants
#define N0 100000
#define N1 50000
#define N2 25000
#define N3 12500
#define E0 800000
#define E1 400000
#define E2 200000
#define D  256

// ---------------- scratch (device globals; no allocation allowed) ----------
__device__ float g_sum[N1 * D];   // per-layer aggregation buffer (max N1 rows)
__device__ float g_cnt[N1];       // per-dst edge counts
__device__ float g_h1[N1 * D];    // layer-0 output
__device__ float g_h2[N2 * D];    // layer-1 output
__device__ int   g_is64;          // edge-index dtype flag (1 = int64, 0 = int32)

// ---------------- dtype detection ------------------------------------------
// Reference does .astype(jnp.int64) but default JAX (x64 off) demotes to int32.
// If the buffer is int64 little-endian with values < 100000, every odd int32
// word is 0. If int32, odd words are random src indices — probability all 32
// samples are 0 is (1/N0)^32 ~ 0.
__global__ void detect_kernel(const int* __restrict__ e) {
    if (blockIdx.x == 0 && threadIdx.x == 0) {
        int is64 = 1;
        for (int i = 1; i < 64; i += 2)
            if (e[i] != 0) is64 = 0;
        g_is64 = is64;
    }
}

// ---------------- zero scratch ----------------------------------------------
__global__ void zero_kernel(float* __restrict__ sum, float* __restrict__ cnt, int M) {
    int n = M * D;
    int stride = gridDim.x * blockDim.x;
    for (int i = blockIdx.x * blockDim.x + threadIdx.x; i < n; i += stride)
        sum[i] = 0.0f;
    for (int i = blockIdx.x * blockDim.x + threadIdx.x; i < M; i += stride)
        cnt[i] = 0.0f;
}

// ---------------- edge scatter: one warp per edge ---------------------------
__global__ void scatter_kernel(const float* __restrict__ h,
                               const void* __restrict__ eraw,
                               int E,
                               float* __restrict__ sum,
                               float* __restrict__ cnt) {
    int gw   = (blockIdx.x * blockDim.x + threadIdx.x) >> 5;
    int lane = threadIdx.x & 31;
    if (gw >= E) return;

    long long s, d;
    if (g_is64) {
        const long long* e = (const long long*)eraw;
        s = e[gw];
        d = e[(long long)E + gw];
    } else {
        const int* e = (const int*)eraw;
        s = e[gw];
        d = e[E + gw];
    }

    const float4* hrow = (const float4*)(h + s * D);
    float* srow = sum + d * D;

#pragma unroll
    for (int i = 0; i < 2; i++) {
        int idx = lane + 32 * i;            // 0..63 float4 slots
        float4 v = hrow[idx];
        float* p = srow + idx * 4;
        atomicAdd(p + 0, v.x);
        atomicAdd(p + 1, v.y);
        atomicAdd(p + 2, v.z);
        atomicAdd(p + 3, v.w);
    }
    if (lane == 0) atomicAdd(cnt + d, 1.0f);
}

// ---------------- mean finalize ----------------------------------------------
__global__ void mean_kernel(float* __restrict__ sum, const float* __restrict__ cnt, int M) {
    int idx = blockIdx.x * blockDim.x + threadIdx.x;
    if (idx >= M * D) return;
    float c = cnt[idx >> 8];
    if (c > 1.0f) sum[idx] = sum[idx] / c;
}

// ---------------- fused SAGE GEMM -------------------------------------------
// C[m,n] = sum_k A1[m,k]*Wl[k,n] + sum_k A2[m,k]*Wr[k,n] + b[n]  (optional ReLU)
// 64x64 block tile, 256 threads, 4x4 per thread, BK=16.
__global__ void __launch_bounds__(256)
sage_gemm_kernel(const float* __restrict__ A1,   // [M, 256] mean
                 const float* __restrict__ A2,   // [M, 256] h_dst (rows 0..M-1)
                 const float* __restrict__ Wl,   // [256, 256]
                 const float* __restrict__ Wr,   // [256, 256]
                 const float* __restrict__ bias, // [256]
                 float* __restrict__ C,          // [M, 256]
                 int M, int do_relu) {
    __shared__ float As[64][16];
    __shared__ float Bs[16][64];

    const int tid = threadIdx.x;
    const int tr  = tid >> 4;   // 0..15
    const int tc  = tid & 15;   // 0..15
    const int row0 = blockIdx.y * 64;
    const int col0 = blockIdx.x * 64;

    const int lrow = tid >> 2;  // 0..63 : A-tile row this thread loads
    const int lk4  = tid & 3;   // float4 slot within 16-wide K
    const int brow = tid >> 4;  // 0..15 : B-tile k-row
    const int bc4  = tid & 15;  // float4 slot within 64-wide N

    float acc[4][4];
#pragma unroll
    for (int i = 0; i < 4; i++)
#pragma unroll
        for (int j = 0; j < 4; j++) acc[i][j] = 0.0f;

    const int arow = row0 + lrow;

#pragma unroll
    for (int phase = 0; phase < 2; phase++) {
        const float* A = phase ? A2 : A1;
        const float* B = phase ? Wr : Wl;
        for (int k0 = 0; k0 < D; k0 += 16) {
            float4 av = make_float4(0.f, 0.f, 0.f, 0.f);
            if (arow < M)
                av = *(const float4*)(A + (size_t)arow * D + k0 + lk4 * 4);
            *(float4*)&As[lrow][lk4 * 4] = av;
            *(float4*)&Bs[brow][bc4 * 4] =
                *(const float4*)(B + (size_t)(k0 + brow) * D + col0 + bc4 * 4);
            __syncthreads();
#pragma unroll
            for (int k = 0; k < 16; k++) {
                float a0 = As[tr * 4 + 0][k];
                float a1 = As[tr * 4 + 1][k];
                float a2 = As[tr * 4 + 2][k];
                float a3 = As[tr * 4 + 3][k];
                float4 bv = *(const float4*)&Bs[k][tc * 4];
                acc[0][0] += a0 * bv.x; acc[0][1] += a0 * bv.y;
                acc[0][2] += a0 * bv.z; acc[0][3] += a0 * bv.w;
                acc[1][0] += a1 * bv.x; acc[1][1] += a1 * bv.y;
                acc[1][2] += a1 * bv.z; acc[1][3] += a1 * bv.w;
                acc[2][0] += a2 * bv.x; acc[2][1] += a2 * bv.y;
                acc[2][2] += a2 * bv.z; acc[2][3] += a2 * bv.w;
                acc[3][0] += a3 * bv.x; acc[3][1] += a3 * bv.y;
                acc[3][2] += a3 * bv.z; acc[3][3] += a3 * bv.w;
            }
            __syncthreads();
        }
    }

    float4 bb = *(const float4*)(bias + col0 + tc * 4);
#pragma unroll
    for (int i = 0; i < 4; i++) {
        int r = row0 + tr * 4 + i;
        if (r < M) {
            float4 v;
            v.x = acc[i][0] + bb.x;
            v.y = acc[i][1] + bb.y;
            v.z = acc[i][2] + bb.z;
            v.w = acc[i][3] + bb.w;
            if (do_relu) {
                v.x = fmaxf(v.x, 0.f);
                v.y = fmaxf(v.y, 0.f);
                v.z = fmaxf(v.z, 0.f);
                v.w = fmaxf(v.w, 0.f);
            }
            *(float4*)(C + (size_t)r * D + col0 + tc * 4) = v;
        }
    }
}

// ---------------- launch -----------------------------------------------------
extern "C" void kernel_launch(void* const* d_in, const int* in_sizes, int n_in,
                              void* d_out, int out_size) {
    const float* x   = (const float*)d_in[0];
    const void*  e0  = d_in[1];
    const void*  e1  = d_in[2];
    const void*  e2  = d_in[3];
    const float* Wl0 = (const float*)d_in[4];
    const float* b0  = (const float*)d_in[5];
    const float* Wr0 = (const float*)d_in[6];
    const float* Wl1 = (const float*)d_in[7];
    const float* b1  = (const float*)d_in[8];
    const float* Wr1 = (const float*)d_in[9];
    const float* Wl2 = (const float*)d_in[10];
    const float* b2  = (const float*)d_in[11];
    const float* Wr2 = (const float*)d_in[12];
    float* out = (float*)d_out;

    float *sum, *cnt, *h1, *h2;
    cudaGetSymbolAddress((void**)&sum, g_sum);
    cudaGetSymbolAddress((void**)&cnt, g_cnt);
    cudaGetSymbolAddress((void**)&h1,  g_h1);
    cudaGetSymbolAddress((void**)&h2,  g_h2);

    detect_kernel<<<1, 32>>>((const int*)e0);

    // ---- layer 0: x[N0] -> h1[N1]
    zero_kernel<<<1024, 256>>>(sum, cnt, N1);
    scatter_kernel<<<(E0 + 7) / 8, 256>>>(x, e0, E0, sum, cnt);
    mean_kernel<<<(N1 * D + 255) / 256, 256>>>(sum, cnt, N1);
    sage_gemm_kernel<<<dim3(D / 64, (N1 + 63) / 64), 256>>>(
        sum, x, Wl0, Wr0, b0, h1, N1, 1);

    // ---- layer 1: h1[N1] -> h2[N2]
    zero_kernel<<<1024, 256>>>(sum, cnt, N2);
    scatter_kernel<<<(E1 + 7) / 8, 256>>>(h1, e1, E1, sum, cnt);
    mean_kernel<<<(N2 * D + 255) / 256, 256>>>(sum, cnt, N2);
    sage_gemm_kernel<<<dim3(D / 64, (N2 + 63) / 64), 256>>>(
        sum, h1, Wl1, Wr1, b1, h2, N2, 1);

    // ---- layer 2: h2[N2] -> out[N3] (no ReLU)
    zero_kernel<<<1024, 256>>>(sum, cnt, N3);
    scatter_kernel<<<(E2 + 7) / 8, 256>>>(h2, e2, E2, sum, cnt);
    mean_kernel<<<(N3 * D + 255) / 256, 256>>>(sum, cnt, N3);
    sage_gemm_kernel<<<dim3(D / 64, (N3 + 63) / 64), 256>>>(
        sum, h2, Wl2, Wr2, b2, out, N3, 0);
}

// round 2
// speedup vs baseline: 2.7207x; 2.7207x over previous
#include <cuda_runtime.h>
#include <cstdint>

// Problem constants
#define N0 100000
#define N1 50000
#define N2 25000
#define N3 12500
#define E0 800000
#define E1 400000
#define E2 200000
#define D  256

// ---------------- scratch (device globals; no allocation allowed) ----------
__device__ float g_sum[N1 * D];   // per-layer aggregation buffer (max N1 rows)
__device__ float g_cnt[N1];       // per-dst edge counts
__device__ float g_h1[N1 * D];    // layer-0 output
__device__ float g_h2[N2 * D];    // layer-1 output
__device__ int   g_is64;          // edge-index dtype flag (1 = int64, 0 = int32)

// ---------------- dtype detection ------------------------------------------
__global__ void detect_kernel(const int* __restrict__ e) {
    if (blockIdx.x == 0 && threadIdx.x == 0) {
        int is64 = 1;
        for (int i = 1; i < 64; i += 2)
            if (e[i] != 0) is64 = 0;
        g_is64 = is64;
    }
}

// ---------------- zero scratch ----------------------------------------------
__global__ void zero_kernel(float* __restrict__ sum, float* __restrict__ cnt, int M) {
    int n = M * D;
    int stride = gridDim.x * blockDim.x;
    for (int i = blockIdx.x * blockDim.x + threadIdx.x; i < n; i += stride)
        sum[i] = 0.0f;
    for (int i = blockIdx.x * blockDim.x + threadIdx.x; i < M; i += stride)
        cnt[i] = 0.0f;
}

// ---------------- edge scatter: one warp per edge, v4 reductions ------------
__device__ __forceinline__ void red_add_v4(float* p, float4 v) {
    asm volatile("red.global.add.v4.f32 [%0], {%1,%2,%3,%4};"
                 :: "l"(p), "f"(v.x), "f"(v.y), "f"(v.z), "f"(v.w)
                 : "memory");
}

__global__ void scatter_kernel(const float* __restrict__ h,
                               const void* __restrict__ eraw,
                               int E,
                               float* __restrict__ sum,
                               float* __restrict__ cnt) {
    int gw   = (blockIdx.x * blockDim.x + threadIdx.x) >> 5;
    int lane = threadIdx.x & 31;
    if (gw >= E) return;

    long long s, d;
    if (g_is64) {
        const long long* e = (const long long*)eraw;
        s = e[gw];
        d = e[(long long)E + gw];
    } else {
        const int* e = (const int*)eraw;
        s = e[gw];
        d = e[E + gw];
    }

    const float4* hrow = (const float4*)(h + s * D);
    float* srow = sum + d * D;

#pragma unroll
    for (int i = 0; i < 2; i++) {
        int idx = lane + 32 * i;            // 0..63 float4 slots
        float4 v = hrow[idx];
        red_add_v4(srow + idx * 4, v);
    }
    if (lane == 0) atomicAdd(cnt + d, 1.0f);
}

// ---------------- fused SAGE GEMM (TF32 tensor cores) -----------------------
// C[m,n] = (sum[m]/max(cnt[m],1)) @ Wl + h_dst[m] @ Wr + b   (optional ReLU)
// Block tile 128x128, 256 threads (8 warps, 4x2 warp grid), warp tile 32x64.
// mma.sync.aligned.m16n8k8 tf32, fp32 accumulate.

#define AS_STRIDE 20
#define BS_STRIDE 136

__device__ __forceinline__ unsigned f2tf(float f) {
    unsigned u;
    asm("cvt.rna.tf32.f32 %0, %1;" : "=r"(u) : "f"(f));
    return u;
}
__device__ __forceinline__ unsigned fu(float f) { return __float_as_uint(f); }

__device__ __forceinline__ void mma_tf32(float c[4], const unsigned a[4],
                                         unsigned b0, unsigned b1) {
    asm volatile(
        "mma.sync.aligned.m16n8k8.row.col.f32.tf32.tf32.f32 "
        "{%0,%1,%2,%3}, {%4,%5,%6,%7}, {%8,%9}, {%0,%1,%2,%3};"
        : "+f"(c[0]), "+f"(c[1]), "+f"(c[2]), "+f"(c[3])
        : "r"(a[0]), "r"(a[1]), "r"(a[2]), "r"(a[3]), "r"(b0), "r"(b1));
}

__global__ void __launch_bounds__(256)
sage_gemm_tc(const float* __restrict__ A1,   // [M, 256] sums
             const float* __restrict__ A2,   // [M, 256] h_dst
             const float* __restrict__ cnt,  // [M]
             const float* __restrict__ Wl,   // [256, 256]
             const float* __restrict__ Wr,   // [256, 256]
             const float* __restrict__ bias, // [256]
             float* __restrict__ C,          // [M, 256]
             int M, int do_relu) {
    __shared__ float As[128 * AS_STRIDE];
    __shared__ float Bs[16 * BS_STRIDE];

    const int tid  = threadIdx.x;
    const int lane = tid & 31;
    const int warp = tid >> 5;
    const int wm   = warp >> 1;        // 0..3 -> m offset *32
    const int wn   = warp & 1;         // 0..1 -> n offset *64
    const int row0 = blockIdx.y * 128;
    const int col0 = blockIdx.x * 128;

    // loader mapping
    const int arow_l = tid >> 1;            // 0..127
    const int akslot = (tid & 1) * 8;       // 0 or 8
    const int brow_l = tid >> 4;            // 0..15
    const int bcol_l = (tid & 15) * 8;      // 0..120

    const int garow = row0 + arow_l;
    float rcp = 1.0f;
    if (garow < M) rcp = 1.0f / fmaxf(cnt[garow], 1.0f);

    float acc[2][8][4];
#pragma unroll
    for (int mi = 0; mi < 2; mi++)
#pragma unroll
        for (int ni = 0; ni < 8; ni++)
#pragma unroll
            for (int j = 0; j < 4; j++) acc[mi][ni][j] = 0.0f;

    const int lr = lane >> 2;   // 0..7
    const int lc = lane & 3;    // 0..3

#pragma unroll
    for (int phase = 0; phase < 2; phase++) {
        const float* A = phase ? A2 : A1;
        const float* B = phase ? Wr : Wl;
        const float scale = phase ? 1.0f : rcp;

        for (int k0 = 0; k0 < D; k0 += 16) {
            // stage A tile (with mean scaling + tf32 round)
#pragma unroll
            for (int h = 0; h < 2; h++) {
                float4 v = make_float4(0.f, 0.f, 0.f, 0.f);
                if (garow < M)
                    v = *(const float4*)(A + (size_t)garow * D + k0 + akslot + h * 4);
                float* p = &As[arow_l * AS_STRIDE + akslot + h * 4];
                p[0] = __uint_as_float(f2tf(v.x * scale));
                p[1] = __uint_as_float(f2tf(v.y * scale));
                p[2] = __uint_as_float(f2tf(v.z * scale));
                p[3] = __uint_as_float(f2tf(v.w * scale));
            }
            // stage B tile
#pragma unroll
            for (int h = 0; h < 2; h++) {
                float4 w = *(const float4*)(B + (size_t)(k0 + brow_l) * D + col0 + bcol_l + h * 4);
                float* p = &Bs[brow_l * BS_STRIDE + bcol_l + h * 4];
                p[0] = __uint_as_float(f2tf(w.x));
                p[1] = __uint_as_float(f2tf(w.y));
                p[2] = __uint_as_float(f2tf(w.z));
                p[3] = __uint_as_float(f2tf(w.w));
            }
            __syncthreads();

#pragma unroll
            for (int ks = 0; ks < 2; ks++) {
                const int k8 = ks * 8;
                unsigned a[2][4];
#pragma unroll
                for (int mi = 0; mi < 2; mi++) {
                    const int rb = wm * 32 + mi * 16 + lr;
                    a[mi][0] = fu(As[rb * AS_STRIDE + k8 + lc]);
                    a[mi][1] = fu(As[(rb + 8) * AS_STRIDE + k8 + lc]);
                    a[mi][2] = fu(As[rb * AS_STRIDE + k8 + lc + 4]);
                    a[mi][3] = fu(As[(rb + 8) * AS_STRIDE + k8 + lc + 4]);
                }
#pragma unroll
                for (int ni = 0; ni < 8; ni++) {
                    const int nb = wn * 64 + ni * 8 + lr;
                    unsigned b0 = fu(Bs[(k8 + lc) * BS_STRIDE + nb]);
                    unsigned b1 = fu(Bs[(k8 + lc + 4) * BS_STRIDE + nb]);
                    mma_tf32(acc[0][ni], a[0], b0, b1);
                    mma_tf32(acc[1][ni], a[1], b0, b1);
                }
            }
            __syncthreads();
        }
    }

    // epilogue: bias (+ReLU) and store
#pragma unroll
    for (int mi = 0; mi < 2; mi++) {
        const int r = row0 + wm * 32 + mi * 16 + lr;
#pragma unroll
        for (int ni = 0; ni < 8; ni++) {
            const int cidx = col0 + wn * 64 + ni * 8 + lc * 2;
            const float bb0 = bias[cidx];
            const float bb1 = bias[cidx + 1];
            float v0 = acc[mi][ni][0] + bb0;
            float v1 = acc[mi][ni][1] + bb1;
            float v2 = acc[mi][ni][2] + bb0;
            float v3 = acc[mi][ni][3] + bb1;
            if (do_relu) {
                v0 = fmaxf(v0, 0.f); v1 = fmaxf(v1, 0.f);
                v2 = fmaxf(v2, 0.f); v3 = fmaxf(v3, 0.f);
            }
            if (r < M) {
                C[(size_t)r * D + cidx]     = v0;
                C[(size_t)r * D + cidx + 1] = v1;
            }
            if (r + 8 < M) {
                C[(size_t)(r + 8) * D + cidx]     = v2;
                C[(size_t)(r + 8) * D + cidx + 1] = v3;
            }
        }
    }
}

// ---------------- launch -----------------------------------------------------
extern "C" void kernel_launch(void* const* d_in, const int* in_sizes, int n_in,
                              void* d_out, int out_size) {
    const float* x   = (const float*)d_in[0];
    const void*  e0  = d_in[1];
    const void*  e1  = d_in[2];
    const void*  e2  = d_in[3];
    const float* Wl0 = (const float*)d_in[4];
    const float* b0  = (const float*)d_in[5];
    const float* Wr0 = (const float*)d_in[6];
    const float* Wl1 = (const float*)d_in[7];
    const float* b1  = (const float*)d_in[8];
    const float* Wr1 = (const float*)d_in[9];
    const float* Wl2 = (const float*)d_in[10];
    const float* b2  = (const float*)d_in[11];
    const float* Wr2 = (const float*)d_in[12];
    float* out = (float*)d_out;

    float *sum, *cnt, *h1, *h2;
    cudaGetSymbolAddress((void**)&sum, g_sum);
    cudaGetSymbolAddress((void**)&cnt, g_cnt);
    cudaGetSymbolAddress((void**)&h1,  g_h1);
    cudaGetSymbolAddress((void**)&h2,  g_h2);

    detect_kernel<<<1, 32>>>((const int*)e0);

    // ---- layer 0: x[N0] -> h1[N1]
    zero_kernel<<<1024, 256>>>(sum, cnt, N1);
    scatter_kernel<<<(E0 + 7) / 8, 256>>>(x, e0, E0, sum, cnt);
    sage_gemm_tc<<<dim3(2, (N1 + 127) / 128), 256>>>(
        sum, x, cnt, Wl0, Wr0, b0, h1, N1, 1);

    // ---- layer 1: h1[N1] -> h2[N2]
    zero_kernel<<<1024, 256>>>(sum, cnt, N2);
    scatter_kernel<<<(E1 + 7) / 8, 256>>>(h1, e1, E1, sum, cnt);
    sage_gemm_tc<<<dim3(2, (N2 + 127) / 128), 256>>>(
        sum, h1, cnt, Wl1, Wr1, b1, h2, N2, 1);

    // ---- layer 2: h2[N2] -> out[N3] (no ReLU)
    zero_kernel<<<1024, 256>>>(sum, cnt, N3);
    scatter_kernel<<<(E2 + 7) / 8, 256>>>(h2, e2, E2, sum, cnt);
    sage_gemm_tc<<<dim3(2, (N3 + 127) / 128), 256>>>(
        sum, h2, cnt, Wl2, Wr2, b2, out, N3, 0);
}